// round 1
// baseline (speedup 1.0000x reference)
#include <cuda_runtime.h>
#include <cuda_bf16.h>
#include <math.h>

// ---------------- problem constants ----------------
#define BB    4
#define TT    4096
#define DD    2048
#define MM    64
#define DZ    512
#define HH    16
#define DH    128
#define DFF   8192
#define BT    (BB*TT)     // 16384
#define BM_   (BB*MM)     // 256

// ---------------- device scratch (allowed: __device__ globals) ----------------
__device__ float g_hn [BT * DD];        // LN output, tf32-rounded
__device__ float g_z  [BM_ * DZ];       // z, tf32-rounded
__device__ float g_Wq [DD * DD];
__device__ float g_Wk [DZ * DD];
__device__ float g_Wv [DZ * DD];
__device__ float g_W1 [DD * DFF];
__device__ float g_W2 [DFF * DD];
__device__ float g_Q  [BT * DD];        // fp32
__device__ float g_K  [BM_ * DD];
__device__ float g_V  [BM_ * DD];
__device__ float g_ctx[BT * DD];        // tf32-rounded
__device__ float g_G  [BT * DFF];       // gelu output, tf32-rounded

// ---------------- helpers ----------------
__device__ __forceinline__ float tf32r(float x) {
    unsigned r;
    asm("cvt.rna.tf32.f32 %0, %1;" : "=r"(r) : "f"(x));
    return __uint_as_float(r);
}

__device__ __forceinline__ float gelu_exact(float x) {
    return 0.5f * x * (1.f + erff(x * 0.70710678118654752440f));
}

__device__ __forceinline__ void cp_async16(void* smem, const void* gmem) {
    unsigned s = (unsigned)__cvta_generic_to_shared(smem);
    asm volatile("cp.async.cg.shared.global [%0], [%1], 16;" :: "r"(s), "l"(gmem));
}
__device__ __forceinline__ void cp_commit() {
    asm volatile("cp.async.commit_group;");
}
__device__ __forceinline__ void cp_wait_all() {
    asm volatile("cp.async.wait_group 0;");
}

__device__ __forceinline__ void mma_tf32(float& c0, float& c1, float& c2, float& c3,
                                         unsigned a0, unsigned a1, unsigned a2, unsigned a3,
                                         unsigned b0, unsigned b1) {
    asm volatile(
        "mma.sync.aligned.m16n8k8.row.col.f32.tf32.tf32.f32 "
        "{%0,%1,%2,%3}, {%4,%5,%6,%7}, {%8,%9}, {%0,%1,%2,%3};"
        : "+f"(c0), "+f"(c1), "+f"(c2), "+f"(c3)
        : "r"(a0), "r"(a1), "r"(a2), "r"(a3), "r"(b0), "r"(b1));
}

// ---------------- elementwise tf32 round ----------------
__global__ void round_tf32_kernel(const float* __restrict__ in, float* __restrict__ out, int n4) {
    int i = blockIdx.x * blockDim.x + threadIdx.x;
    if (i < n4) {
        float4 v = ((const float4*)in)[i];
        v.x = tf32r(v.x); v.y = tf32r(v.y); v.z = tf32r(v.z); v.w = tf32r(v.w);
        ((float4*)out)[i] = v;
    }
}

// ---------------- LayerNorm: 1 row per block, 256 threads ----------------
__global__ __launch_bounds__(256) void ln_kernel(
    const float* __restrict__ h, const float* __restrict__ g,
    const float* __restrict__ b, float* __restrict__ out)
{
    int row = blockIdx.x;
    const float4* x4 = (const float4*)(h + (size_t)row * DD);
    int tx = threadIdx.x;
    float4 v0 = x4[tx], v1 = x4[tx + 256];
    float s  = v0.x + v0.y + v0.z + v0.w + v1.x + v1.y + v1.z + v1.w;
    float s2 = v0.x*v0.x + v0.y*v0.y + v0.z*v0.z + v0.w*v0.w
             + v1.x*v1.x + v1.y*v1.y + v1.z*v1.z + v1.w*v1.w;
    int lane = tx & 31, warp = tx >> 5;
    #pragma unroll
    for (int o = 16; o; o >>= 1) {
        s  += __shfl_xor_sync(0xffffffffu, s,  o);
        s2 += __shfl_xor_sync(0xffffffffu, s2, o);
    }
    __shared__ float sh[16];
    if (lane == 0) { sh[warp] = s; sh[warp + 8] = s2; }
    __syncthreads();
    float ts = 0.f, ts2 = 0.f;
    #pragma unroll
    for (int i = 0; i < 8; i++) { ts += sh[i]; ts2 += sh[i + 8]; }
    float mu  = ts * (1.f / DD);
    float var = ts2 * (1.f / DD) - mu * mu;
    float inv = rsqrtf(var + 1e-5f);

    const float4* g4 = (const float4*)g;
    const float4* b4 = (const float4*)b;
    float4* o4 = (float4*)(out + (size_t)row * DD);
    float4 ga = g4[tx], bb = b4[tx];
    float4 y;
    y.x = tf32r((v0.x - mu) * inv * ga.x + bb.x);
    y.y = tf32r((v0.y - mu) * inv * ga.y + bb.y);
    y.z = tf32r((v0.z - mu) * inv * ga.z + bb.z);
    y.w = tf32r((v0.w - mu) * inv * ga.w + bb.w);
    o4[tx] = y;
    ga = g4[tx + 256]; bb = b4[tx + 256];
    y.x = tf32r((v1.x - mu) * inv * ga.x + bb.x);
    y.y = tf32r((v1.y - mu) * inv * ga.y + bb.y);
    y.z = tf32r((v1.z - mu) * inv * ga.z + bb.z);
    y.w = tf32r((v1.w - mu) * inv * ga.w + bb.w);
    o4[tx + 256] = y;
}

// ---------------- TF32 GEMM: C[M,N] = A[M,K] @ W[K,N] (+epilogue) ----------------
// EPI 0: C = acc + bias
// EPI 1: C = tf32(gelu(acc + bias))
// EPI 2: C = res + tanh(*alpha) * (acc + bias)
template<int EPI>
__global__ __launch_bounds__(256, 2) void gemm_tf32(
    const float* __restrict__ A, const float* __restrict__ W,
    const float* __restrict__ bias, float* __restrict__ C,
    int Mdim, int Ndim, int Kdim,
    const float* __restrict__ res, const float* __restrict__ alpha)
{
    constexpr int BMt = 128, BNt = 128, BKt = 16;
    constexpr int ASd = 20;    // A smem stride (floats), conflict-free fragments
    constexpr int BSd = 136;   // B smem stride
    __shared__ float As[2][BMt * ASd];
    __shared__ float Bs[2][BKt * BSd];

    const int bm = blockIdx.y * BMt, bn = blockIdx.x * BNt;
    const int tid = threadIdx.x;
    const int warp = tid >> 5, lane = tid & 31;
    const int wm = (warp >> 2) * 64, wn = (warp & 3) * 32;  // 2x4 warp grid
    const int gid = lane >> 2, t4 = lane & 3;

    float acc[4][4][4];
    #pragma unroll
    for (int i = 0; i < 4; i++)
        #pragma unroll
        for (int j = 0; j < 4; j++)
            #pragma unroll
            for (int k = 0; k < 4; k++) acc[i][j][k] = 0.f;

    const int KT = Kdim / BKt;

    // --- tile loaders (512 x 16B chunks each, 2 per thread) ---
    auto ldA = [&](int kt, int buf) {
        int k0 = kt * BKt;
        #pragma unroll
        for (int i = 0; i < 2; i++) {
            int chunk = tid + i * 256;
            int row = chunk >> 2, c4 = (chunk & 3) * 4;
            cp_async16(&As[buf][row * ASd + c4],
                       A + (size_t)(bm + row) * Kdim + k0 + c4);
        }
    };
    auto ldB = [&](int kt, int buf) {
        int k0 = kt * BKt;
        #pragma unroll
        for (int i = 0; i < 2; i++) {
            int chunk = tid + i * 256;
            int row = chunk >> 5, c4 = (chunk & 31) * 4;
            cp_async16(&Bs[buf][row * BSd + c4],
                       W + (size_t)(k0 + row) * Ndim + bn + c4);
        }
    };

    ldA(0, 0); ldB(0, 0); cp_commit();
    int buf = 0;
    for (int kt = 0; kt < KT; ++kt) {
        cp_wait_all();
        __syncthreads();
        if (kt + 1 < KT) { ldA(kt + 1, buf ^ 1); ldB(kt + 1, buf ^ 1); cp_commit(); }

        #pragma unroll
        for (int ks = 0; ks < 2; ++ks) {
            const int k0 = ks * 8;
            unsigned a[4][4], b[4][2];
            #pragma unroll
            for (int mi = 0; mi < 4; mi++) {
                int r0 = wm + mi * 16;
                a[mi][0] = __float_as_uint(As[buf][(r0 + gid    ) * ASd + k0 + t4    ]);
                a[mi][1] = __float_as_uint(As[buf][(r0 + gid + 8) * ASd + k0 + t4    ]);
                a[mi][2] = __float_as_uint(As[buf][(r0 + gid    ) * ASd + k0 + t4 + 4]);
                a[mi][3] = __float_as_uint(As[buf][(r0 + gid + 8) * ASd + k0 + t4 + 4]);
            }
            #pragma unroll
            for (int ni = 0; ni < 4; ni++) {
                b[ni][0] = __float_as_uint(Bs[buf][(k0 + t4    ) * BSd + wn + ni * 8 + gid]);
                b[ni][1] = __float_as_uint(Bs[buf][(k0 + t4 + 4) * BSd + wn + ni * 8 + gid]);
            }
            #pragma unroll
            for (int mi = 0; mi < 4; mi++)
                #pragma unroll
                for (int ni = 0; ni < 4; ni++)
                    mma_tf32(acc[mi][ni][0], acc[mi][ni][1], acc[mi][ni][2], acc[mi][ni][3],
                             a[mi][0], a[mi][1], a[mi][2], a[mi][3],
                             b[ni][0], b[ni][1]);
        }
        buf ^= 1;
    }

    // --- epilogue ---
    float ta = 0.f;
    if (EPI == 2) ta = tanhf(*alpha);
    #pragma unroll
    for (int mi = 0; mi < 4; mi++) {
        #pragma unroll
        for (int ni = 0; ni < 4; ni++) {
            int col = bn + wn + ni * 8 + t4 * 2;
            float2 bb = *(const float2*)&bias[col];
            #pragma unroll
            for (int hf = 0; hf < 2; hf++) {
                int row = bm + wm + mi * 16 + gid + hf * 8;
                float v0 = acc[mi][ni][hf * 2 + 0] + bb.x;
                float v1 = acc[mi][ni][hf * 2 + 1] + bb.y;
                size_t off = (size_t)row * Ndim + col;
                if (EPI == 1) {
                    v0 = tf32r(gelu_exact(v0));
                    v1 = tf32r(gelu_exact(v1));
                } else if (EPI == 2) {
                    float2 rr = *(const float2*)&res[off];
                    v0 = rr.x + ta * v0;
                    v1 = rr.y + ta * v1;
                }
                float2 o; o.x = v0; o.y = v1;
                *(float2*)&C[off] = o;
            }
        }
    }
}

// ---------------- cross-attention (M=64 keys, dh=128) ----------------
// grid: (T/64, H, B), block 256 threads (8 warps x 8 rows each)
__global__ __launch_bounds__(256) void attn_kernel(
    const float* __restrict__ Q, const float* __restrict__ Kb,
    const float* __restrict__ Vb, float* __restrict__ ctx)
{
    extern __shared__ float sm[];
    float* Qs = sm;                 // [64][128]
    float* Kt = Qs + 64 * 128;      // [128][64]  (d-major, transposed)
    float* Vs = Kt + 128 * 64;      // [64][128]
    float* ws = Vs + 64 * 128;      // [8][64]

    const int b = blockIdx.z, hh = blockIdx.y;
    const int t0 = blockIdx.x * 64;
    const int tid = threadIdx.x;

    for (int i = tid; i < MM * DH; i += 256) {
        int m = i >> 7, d = i & 127;
        size_t kvoff = (size_t)(b * MM + m) * DD + hh * DH + d;
        Kt[d * 64 + m] = Kb[kvoff];
        Vs[i]          = Vb[kvoff];
        Qs[i]          = Q[(size_t)(b * TT + t0 + m) * DD + hh * DH + d];
    }
    __syncthreads();

    const int warp = tid >> 5, lane = tid & 31;
    const float scale = 0.08838834764831844f;   // 1/sqrt(128)

    for (int rr = 0; rr < 8; ++rr) {
        int r = warp * 8 + rr;
        const float* qp = &Qs[r * 128];
        float s0 = 0.f, s1 = 0.f;
        #pragma unroll 8
        for (int d = 0; d < 128; ++d) {
            float q = qp[d];
            float2 kk = *(const float2*)&Kt[d * 64 + lane * 2];
            s0 = fmaf(q, kk.x, s0);
            s1 = fmaf(q, kk.y, s1);
        }
        s0 *= scale; s1 *= scale;
        float mx = fmaxf(s0, s1);
        #pragma unroll
        for (int o = 16; o; o >>= 1) mx = fmaxf(mx, __shfl_xor_sync(0xffffffffu, mx, o));
        float e0 = expf(s0 - mx), e1 = expf(s1 - mx);
        float sum = e0 + e1;
        #pragma unroll
        for (int o = 16; o; o >>= 1) sum += __shfl_xor_sync(0xffffffffu, sum, o);
        float inv = 1.f / sum;
        ws[warp * 64 + lane * 2    ] = e0 * inv;
        ws[warp * 64 + lane * 2 + 1] = e1 * inv;
        __syncwarp();

        float4 a; a.x = a.y = a.z = a.w = 0.f;
        #pragma unroll 8
        for (int m = 0; m < 64; ++m) {
            float w = ws[warp * 64 + m];
            float4 v = *(const float4*)&Vs[m * 128 + lane * 4];
            a.x = fmaf(w, v.x, a.x); a.y = fmaf(w, v.y, a.y);
            a.z = fmaf(w, v.z, a.z); a.w = fmaf(w, v.w, a.w);
        }
        a.x = tf32r(a.x); a.y = tf32r(a.y); a.z = tf32r(a.z); a.w = tf32r(a.w);
        *(float4*)&ctx[(size_t)(b * TT + t0 + r) * DD + hh * DH + lane * 4] = a;
        __syncwarp();
    }
}

// ---------------- launch ----------------
static float* sym_addr(const void* sym) {
    void* p = nullptr;
    cudaGetSymbolAddress(&p, sym);
    return (float*)p;
}

extern "C" void kernel_launch(void* const* d_in, const int* in_sizes, int n_in,
                              void* d_out, int out_size)
{
    const float* h    = (const float*)d_in[0];
    const float* z    = (const float*)d_in[1];
    const float* ln_g = (const float*)d_in[2];
    const float* ln_b = (const float*)d_in[3];
    const float* Wq   = (const float*)d_in[4];
    const float* bq   = (const float*)d_in[5];
    const float* Wk   = (const float*)d_in[6];
    const float* bk   = (const float*)d_in[7];
    const float* Wv   = (const float*)d_in[8];
    const float* bv   = (const float*)d_in[9];
    const float* W1   = (const float*)d_in[10];
    const float* b1   = (const float*)d_in[11];
    const float* W2   = (const float*)d_in[12];
    const float* b2   = (const float*)d_in[13];
    const float* alpha= (const float*)d_in[14];
    float* out = (float*)d_out;

    float* hn  = sym_addr(g_hn);
    float* zr  = sym_addr(g_z);
    float* wq  = sym_addr(g_Wq);
    float* wk  = sym_addr(g_Wk);
    float* wv  = sym_addr(g_Wv);
    float* w1  = sym_addr(g_W1);
    float* w2  = sym_addr(g_W2);
    float* qb  = sym_addr(g_Q);
    float* kb  = sym_addr(g_K);
    float* vb  = sym_addr(g_V);
    float* cx  = sym_addr(g_ctx);
    float* gb  = sym_addr(g_G);

    auto roundN = [&](const float* src, float* dst, int n) {
        int n4 = n / 4;
        round_tf32_kernel<<<(n4 + 255) / 256, 256>>>(src, dst, n4);
    };

    // 1) pre-round all GEMM operands to tf32 (rna)
    roundN(Wq, wq, DD * DD);
    roundN(Wk, wk, DZ * DD);
    roundN(Wv, wv, DZ * DD);
    roundN(W1, w1, DD * DFF);
    roundN(W2, w2, DFF * DD);
    roundN(z,  zr, BM_ * DZ);

    // 2) LayerNorm (rounds output to tf32)
    ln_kernel<<<BT, 256>>>(h, ln_g, ln_b, hn);

    // 3) projections
    gemm_tf32<0><<<dim3(DD / 128, BT / 128), 256>>>(hn, wq, bq, qb, BT, DD, DD, nullptr, nullptr);
    gemm_tf32<0><<<dim3(DD / 128, BM_ / 128), 256>>>(zr, wk, bk, kb, BM_, DD, DZ, nullptr, nullptr);
    gemm_tf32<0><<<dim3(DD / 128, BM_ / 128), 256>>>(zr, wv, bv, vb, BM_, DD, DZ, nullptr, nullptr);

    // 4) cross attention -> ctx (tf32-rounded)
    {
        int smem = (3 * 64 * 128 + 8 * 64) * (int)sizeof(float);  // ~100 KB
        cudaFuncSetAttribute(attn_kernel, cudaFuncAttributeMaxDynamicSharedMemorySize, smem);
        attn_kernel<<<dim3(TT / 64, HH, BB), 256, smem>>>(qb, kb, vb, cx);
    }

    // 5) FFN1 with fused exact-GELU (output tf32-rounded)
    gemm_tf32<1><<<dim3(DFF / 128, BT / 128), 256>>>(cx, w1, b1, gb, BT, DFF, DD, nullptr, nullptr);

    // 6) FFN2 with fused residual: out = h + tanh(alpha)*(G@W2 + b2)
    gemm_tf32<2><<<dim3(DD / 128, BT / 128), 256>>>(gb, w2, b2, out, BT, DD, DFF, h, alpha);
}

// round 3
// speedup vs baseline: 2.2787x; 2.2787x over previous
#include <cuda_runtime.h>
#include <cuda_fp16.h>
#include <math.h>
#include <stdint.h>

// ---------------- problem constants ----------------
#define BB    4
#define TT    4096
#define DD    2048
#define MM    64
#define DZ    512
#define HH    16
#define DH    128
#define DFF   8192
#define BT    (BB*TT)     // 16384
#define BM_   (BB*MM)     // 256

// ---------------- device scratch ----------------
__device__ __half g_hn [BT * DD];        // LN output (fp16)
__device__ __half g_z  [BM_ * DZ];       // z (fp16)
__device__ __half g_WqT[DD * DD];        // [N=D, K=D]   K-major
__device__ __half g_WkT[DD * DZ];        // [N=D, K=Dz]
__device__ __half g_WvT[DD * DZ];
__device__ __half g_W1T[DFF * DD];       // [N=Dff, K=D]
__device__ __half g_W2T[DD * DFF];       // [N=D, K=Dff]
__device__ float  g_Q  [BT * DD];        // fp32 for attention
__device__ float  g_K  [BM_ * DD];
__device__ float  g_V  [BM_ * DD];
__device__ __half g_ctx[BT * DD];        // attention output (fp16)
__device__ __half g_G  [BT * DFF];       // gelu output (fp16)

// ---------------- helpers ----------------
__device__ __forceinline__ float gelu_exact(float x) {
    return 0.5f * x * (1.f + erff(x * 0.70710678118654752440f));
}
__device__ __forceinline__ void cp_async16(uint32_t s, const void* g) {
    asm volatile("cp.async.cg.shared.global [%0], [%1], 16;" :: "r"(s), "l"(g));
}
__device__ __forceinline__ void cp_commit() {
    asm volatile("cp.async.commit_group;");
}
template<int N> __device__ __forceinline__ void cp_wait() {
    asm volatile("cp.async.wait_group %0;" :: "n"(N));
}
__device__ __forceinline__ void ldsm4(uint32_t& r0, uint32_t& r1, uint32_t& r2, uint32_t& r3,
                                      uint32_t addr) {
    asm volatile("ldmatrix.sync.aligned.m8n8.x4.shared.b16 {%0,%1,%2,%3}, [%4];"
        : "=r"(r0), "=r"(r1), "=r"(r2), "=r"(r3) : "r"(addr));
}
__device__ __forceinline__ void mma16816(float* c,
                                         uint32_t a0, uint32_t a1, uint32_t a2, uint32_t a3,
                                         uint32_t b0, uint32_t b1) {
    asm volatile(
        "mma.sync.aligned.m16n8k16.row.col.f32.f16.f16.f32 "
        "{%0,%1,%2,%3}, {%4,%5,%6,%7}, {%8,%9}, {%0,%1,%2,%3};"
        : "+f"(c[0]), "+f"(c[1]), "+f"(c[2]), "+f"(c[3])
        : "r"(a0), "r"(a1), "r"(a2), "r"(a3), "r"(b0), "r"(b1));
}

// ---------------- elementwise fp32 -> fp16 ----------------
__global__ void to_half_kernel(const float* __restrict__ in, __half* __restrict__ out, int n4) {
    int i = blockIdx.x * blockDim.x + threadIdx.x;
    if (i < n4) {
        float4 v = ((const float4*)in)[i];
        __half2 h0 = __floats2half2_rn(v.x, v.y);
        __half2 h1 = __floats2half2_rn(v.z, v.w);
        uint2 o; o.x = *(uint32_t*)&h0; o.y = *(uint32_t*)&h1;
        ((uint2*)out)[i] = o;
    }
}

// ---------------- weight transpose + half: W[K,N] -> Wt[N,K] fp16 ----------------
__global__ __launch_bounds__(256) void transpose_half(
    const float* __restrict__ W, __half* __restrict__ Wt, int K, int N)
{
    __shared__ float t[32][33];
    int n0 = blockIdx.x * 32, k0 = blockIdx.y * 32;
    int tx = threadIdx.x, ty = threadIdx.y;   // 32 x 8
    #pragma unroll
    for (int i = 0; i < 32; i += 8)
        t[ty + i][tx] = W[(size_t)(k0 + ty + i) * N + n0 + tx];
    __syncthreads();
    #pragma unroll
    for (int i = 0; i < 32; i += 8)
        Wt[(size_t)(n0 + ty + i) * K + k0 + tx] = __float2half_rn(t[tx][ty + i]);
}

// ---------------- LayerNorm: fp32 in, fp16 out ----------------
__global__ __launch_bounds__(256) void ln_kernel(
    const float* __restrict__ h, const float* __restrict__ g,
    const float* __restrict__ b, __half* __restrict__ out)
{
    int row = blockIdx.x;
    const float4* x4 = (const float4*)(h + (size_t)row * DD);
    int tx = threadIdx.x;
    float4 v0 = x4[tx], v1 = x4[tx + 256];
    float s  = v0.x + v0.y + v0.z + v0.w + v1.x + v1.y + v1.z + v1.w;
    float s2 = v0.x*v0.x + v0.y*v0.y + v0.z*v0.z + v0.w*v0.w
             + v1.x*v1.x + v1.y*v1.y + v1.z*v1.z + v1.w*v1.w;
    int lane = tx & 31, warp = tx >> 5;
    #pragma unroll
    for (int o = 16; o; o >>= 1) {
        s  += __shfl_xor_sync(0xffffffffu, s,  o);
        s2 += __shfl_xor_sync(0xffffffffu, s2, o);
    }
    __shared__ float sh[16];
    if (lane == 0) { sh[warp] = s; sh[warp + 8] = s2; }
    __syncthreads();
    float ts = 0.f, ts2 = 0.f;
    #pragma unroll
    for (int i = 0; i < 8; i++) { ts += sh[i]; ts2 += sh[i + 8]; }
    float mu  = ts * (1.f / DD);
    float var = ts2 * (1.f / DD) - mu * mu;
    float inv = rsqrtf(var + 1e-5f);

    const float4* g4 = (const float4*)g;
    const float4* b4 = (const float4*)b;
    uint2* o4 = (uint2*)(out + (size_t)row * DD);
    #pragma unroll
    for (int half_i = 0; half_i < 2; half_i++) {
        float4 v = half_i ? v1 : v0;
        int idx = tx + half_i * 256;
        float4 ga = g4[idx], bb = b4[idx];
        float y0 = (v.x - mu) * inv * ga.x + bb.x;
        float y1 = (v.y - mu) * inv * ga.y + bb.y;
        float y2 = (v.z - mu) * inv * ga.z + bb.z;
        float y3 = (v.w - mu) * inv * ga.w + bb.w;
        __half2 h0 = __floats2half2_rn(y0, y1);
        __half2 h1 = __floats2half2_rn(y2, y3);
        uint2 o; o.x = *(uint32_t*)&h0; o.y = *(uint32_t*)&h1;
        o4[idx] = o;
    }
}

// ---------------- fp16 GEMM: C[M,N] = A[M,K] @ Bt[N,K]^T ----------------
// mma.sync m16n8k16, ldmatrix, 128x128x32 tiles, 4-stage cp.async pipeline.
// EPI 0: C(fp32) = acc + bias
// EPI 1: C(fp16) = gelu(acc + bias)
// EPI 2: C(fp32) = res + tanh(*alpha) * (acc + bias)
template<int EPI>
__global__ void __launch_bounds__(256, 2) gemm_fp16(
    const __half* __restrict__ A, const __half* __restrict__ Bt,
    const float* __restrict__ bias, void* __restrict__ Cv,
    int Mdim, int Ndim, int Kdim,
    const float* __restrict__ res, const float* __restrict__ alpha)
{
    constexpr int STAGE = 16384;           // 8KB A + 8KB B per stage
    extern __shared__ __align__(128) char smem[];
    uint32_t sb = (uint32_t)__cvta_generic_to_shared(smem);
    const int tid  = threadIdx.x;
    const int lane = tid & 31, warp = tid >> 5;
    const int wm = (warp & 3) * 32, wn = (warp >> 2) * 64;

    // --- tile coords with grouped-M rasterization ---
    int gm = Mdim >> 7, gn = Ndim >> 7;
    int pid = blockIdx.x;
    const int GRP = 8;
    int width = GRP * gn;
    int grp = pid / width;
    int first = grp * GRP;
    int sz = min(gm - first, GRP);
    int mt = first + (pid % sz);
    int nt = (pid % width) / sz;
    const int bm = mt << 7, bn = nt << 7;

    float acc[2][8][4];
    #pragma unroll
    for (int i = 0; i < 2; i++)
        #pragma unroll
        for (int j = 0; j < 8; j++)
            #pragma unroll
            for (int k = 0; k < 4; k++) acc[i][j][k] = 0.f;

    const int KT = Kdim >> 5;   // k-tiles of 32

    // loader: each thread moves 2 A-chunks + 2 B-chunks of 16B per k-tile
    const int lrow = tid >> 2, lch = tid & 3;
    auto loadTile = [&](int kt) {
        uint32_t base = sb + (kt & 3) * STAGE;
        const __half* Ag = A  + (size_t)bm * Kdim + kt * 32;
        const __half* Bg = Bt + (size_t)bn * Kdim + kt * 32;
        uint32_t sw = (uint32_t)(lch ^ ((lrow >> 1) & 3)) << 4;
        // A rows lrow, lrow+64
        cp_async16(base + lrow * 64 + sw,        Ag + (size_t)lrow * Kdim + lch * 8);
        cp_async16(base + (lrow + 64) * 64 + sw, Ag + (size_t)(lrow + 64) * Kdim + lch * 8);
        // B rows lrow, lrow+64
        uint32_t bbse = base + 8192;
        cp_async16(bbse + lrow * 64 + sw,        Bg + (size_t)lrow * Kdim + lch * 8);
        cp_async16(bbse + (lrow + 64) * 64 + sw, Bg + (size_t)(lrow + 64) * Kdim + lch * 8);
        cp_commit();
    };

    loadTile(0); loadTile(1); loadTile(2);

    // precomputed ldmatrix row indices
    const int ar0 = wm + (lane & 15);                      // A rows (mi=0); +16 for mi=1
    const int brr = wn + (lane & 7) + ((lane >> 4) << 3);  // B base row; +16 per ni
    const int a_l16 = (lane >> 4);                         // A chunk parity
    const int b_l8  = (lane >> 3) & 1;                     // B chunk parity

    for (int kt = 0; kt < KT; ++kt) {
        cp_wait<2>();
        __syncthreads();
        if (kt + 3 < KT) loadTile(kt + 3); else cp_commit();

        uint32_t Ab = sb + (kt & 3) * STAGE;
        uint32_t Bb = Ab + 8192;
        #pragma unroll
        for (int ks = 0; ks < 2; ++ks) {
            uint32_t a[2][4];
            int ach = ks * 2 + a_l16;
            #pragma unroll
            for (int mi = 0; mi < 2; mi++) {
                int r = ar0 + mi * 16;
                uint32_t addr = Ab + r * 64 + (((uint32_t)(ach ^ ((r >> 1) & 3))) << 4);
                ldsm4(a[mi][0], a[mi][1], a[mi][2], a[mi][3], addr);
            }
            int bch = ks * 2 + b_l8;
            #pragma unroll
            for (int ni = 0; ni < 4; ni++) {
                int r = brr + ni * 16;
                uint32_t addr = Bb + r * 64 + (((uint32_t)(bch ^ ((r >> 1) & 3))) << 4);
                uint32_t b0, b1, b2, b3;
                ldsm4(b0, b1, b2, b3, addr);
                #pragma unroll
                for (int mi = 0; mi < 2; mi++) {
                    mma16816(acc[mi][ni * 2    ], a[mi][0], a[mi][1], a[mi][2], a[mi][3], b0, b1);
                    mma16816(acc[mi][ni * 2 + 1], a[mi][0], a[mi][1], a[mi][2], a[mi][3], b2, b3);
                }
            }
        }
    }

    // --- epilogue ---
    float ta = 0.f;
    if (EPI == 2) ta = tanhf(*alpha);
    const int r0 = bm + wm + (lane >> 2);
    const int c0 = bn + wn + (lane & 3) * 2;
    #pragma unroll
    for (int mi = 0; mi < 2; mi++) {
        #pragma unroll
        for (int nj = 0; nj < 8; nj++) {
            int col = c0 + nj * 8;
            float2 bv = *(const float2*)&bias[col];
            #pragma unroll
            for (int hf = 0; hf < 2; hf++) {
                int row = r0 + mi * 16 + hf * 8;
                float v0 = acc[mi][nj][hf * 2    ] + bv.x;
                float v1 = acc[mi][nj][hf * 2 + 1] + bv.y;
                size_t off = (size_t)row * Ndim + col;
                if (EPI == 1) {
                    __half2 hv = __floats2half2_rn(gelu_exact(v0), gelu_exact(v1));
                    *(__half2*)((__half*)Cv + off) = hv;
                } else if (EPI == 2) {
                    float2 rr = *(const float2*)&res[off];
                    float2 o; o.x = rr.x + ta * v0; o.y = rr.y + ta * v1;
                    *(float2*)((float*)Cv + off) = o;
                } else {
                    float2 o; o.x = v0; o.y = v1;
                    *(float2*)((float*)Cv + off) = o;
                }
            }
        }
    }
}

// ---------------- cross-attention (M=64 keys, dh=128), fp32 in, fp16 out ----------------
__global__ __launch_bounds__(256) void attn_kernel(
    const float* __restrict__ Q, const float* __restrict__ Kb,
    const float* __restrict__ Vb, __half* __restrict__ ctx)
{
    extern __shared__ float sm[];
    float* Qs = sm;                 // [64][128]
    float* Kt = Qs + 64 * 128;      // [128][64]
    float* Vs = Kt + 128 * 64;      // [64][128]
    float* ws = Vs + 64 * 128;      // [8][64]

    const int b = blockIdx.z, hh = blockIdx.y;
    const int t0 = blockIdx.x * 64;
    const int tid = threadIdx.x;

    for (int i = tid; i < MM * DH; i += 256) {
        int m = i >> 7, d = i & 127;
        size_t kvoff = (size_t)(b * MM + m) * DD + hh * DH + d;
        Kt[d * 64 + m] = Kb[kvoff];
        Vs[i]          = Vb[kvoff];
        Qs[i]          = Q[(size_t)(b * TT + t0 + m) * DD + hh * DH + d];
    }
    __syncthreads();

    const int warp = tid >> 5, lane = tid & 31;
    const float scale = 0.08838834764831844f;   // 1/sqrt(128)

    for (int rr = 0; rr < 8; ++rr) {
        int r = warp * 8 + rr;
        const float* qp = &Qs[r * 128];
        float s0 = 0.f, s1 = 0.f;
        #pragma unroll 8
        for (int d = 0; d < 128; ++d) {
            float q = qp[d];
            float2 kk = *(const float2*)&Kt[d * 64 + lane * 2];
            s0 = fmaf(q, kk.x, s0);
            s1 = fmaf(q, kk.y, s1);
        }
        s0 *= scale; s1 *= scale;
        float mx = fmaxf(s0, s1);
        #pragma unroll
        for (int o = 16; o; o >>= 1) mx = fmaxf(mx, __shfl_xor_sync(0xffffffffu, mx, o));
        float e0 = expf(s0 - mx), e1 = expf(s1 - mx);
        float sum = e0 + e1;
        #pragma unroll
        for (int o = 16; o; o >>= 1) sum += __shfl_xor_sync(0xffffffffu, sum, o);
        float inv = 1.f / sum;
        ws[warp * 64 + lane * 2    ] = e0 * inv;
        ws[warp * 64 + lane * 2 + 1] = e1 * inv;
        __syncwarp();

        float4 a; a.x = a.y = a.z = a.w = 0.f;
        #pragma unroll 8
        for (int m = 0; m < 64; ++m) {
            float wv = ws[warp * 64 + m];
            float4 v = *(const float4*)&Vs[m * 128 + lane * 4];
            a.x = fmaf(wv, v.x, a.x); a.y = fmaf(wv, v.y, a.y);
            a.z = fmaf(wv, v.z, a.z); a.w = fmaf(wv, v.w, a.w);
        }
        __half2 h0 = __floats2half2_rn(a.x, a.y);
        __half2 h1 = __floats2half2_rn(a.z, a.w);
        uint2 o; o.x = *(uint32_t*)&h0; o.y = *(uint32_t*)&h1;
        *(uint2*)&ctx[(size_t)(b * TT + t0 + r) * DD + hh * DH + lane * 4] = o;
        __syncwarp();
    }
}

// ---------------- launch ----------------
template<typename T>
static T* sym_addr(const void* sym) {
    void* p = nullptr;
    cudaGetSymbolAddress(&p, sym);
    return (T*)p;
}

extern "C" void kernel_launch(void* const* d_in, const int* in_sizes, int n_in,
                              void* d_out, int out_size)
{
    const float* h    = (const float*)d_in[0];
    const float* z    = (const float*)d_in[1];
    const float* ln_g = (const float*)d_in[2];
    const float* ln_b = (const float*)d_in[3];
    const float* Wq   = (const float*)d_in[4];
    const float* bq   = (const float*)d_in[5];
    const float* Wk   = (const float*)d_in[6];
    const float* bk   = (const float*)d_in[7];
    const float* Wv   = (const float*)d_in[8];
    const float* bv   = (const float*)d_in[9];
    const float* W1   = (const float*)d_in[10];
    const float* b1   = (const float*)d_in[11];
    const float* W2   = (const float*)d_in[12];
    const float* b2   = (const float*)d_in[13];
    const float* alpha= (const float*)d_in[14];
    float* out = (float*)d_out;

    __half* hn  = sym_addr<__half>(g_hn);
    __half* zr  = sym_addr<__half>(g_z);
    __half* wqT = sym_addr<__half>(g_WqT);
    __half* wkT = sym_addr<__half>(g_WkT);
    __half* wvT = sym_addr<__half>(g_WvT);
    __half* w1T = sym_addr<__half>(g_W1T);
    __half* w2T = sym_addr<__half>(g_W2T);
    float*  qb  = sym_addr<float>(g_Q);
    float*  kb  = sym_addr<float>(g_K);
    float*  vb  = sym_addr<float>(g_V);
    __half* cx  = sym_addr<__half>(g_ctx);
    __half* gb  = sym_addr<__half>(g_G);

    const int SMEM = 4 * 16384;   // 64KB
    cudaFuncSetAttribute(gemm_fp16<0>, cudaFuncAttributeMaxDynamicSharedMemorySize, SMEM);
    cudaFuncSetAttribute(gemm_fp16<1>, cudaFuncAttributeMaxDynamicSharedMemorySize, SMEM);
    cudaFuncSetAttribute(gemm_fp16<2>, cudaFuncAttributeMaxDynamicSharedMemorySize, SMEM);

    // 1) weight transposes -> [N,K] fp16
    transpose_half<<<dim3(DD / 32, DD / 32),  dim3(32, 8)>>>(Wq, wqT, DD,  DD);
    transpose_half<<<dim3(DD / 32, DZ / 32),  dim3(32, 8)>>>(Wk, wkT, DZ,  DD);
    transpose_half<<<dim3(DD / 32, DZ / 32),  dim3(32, 8)>>>(Wv, wvT, DZ,  DD);
    transpose_half<<<dim3(DFF / 32, DD / 32), dim3(32, 8)>>>(W1, w1T, DD,  DFF);
    transpose_half<<<dim3(DD / 32, DFF / 32), dim3(32, 8)>>>(W2, w2T, DFF, DD);

    // 2) z -> fp16, LayerNorm h -> fp16
    to_half_kernel<<<(BM_ * DZ / 4 + 255) / 256, 256>>>(z, zr, BM_ * DZ / 4);
    ln_kernel<<<BT, 256>>>(h, ln_g, ln_b, hn);

    // 3) projections (fp32 out for attention)
    gemm_fp16<0><<<(BT / 128) * (DD / 128), 256, SMEM>>>(hn, wqT, bq, qb, BT, DD, DD, nullptr, nullptr);
    gemm_fp16<0><<<(BM_ / 128) * (DD / 128), 256, SMEM>>>(zr, wkT, bk, kb, BM_, DD, DZ, nullptr, nullptr);
    gemm_fp16<0><<<(BM_ / 128) * (DD / 128), 256, SMEM>>>(zr, wvT, bv, vb, BM_, DD, DZ, nullptr, nullptr);

    // 4) cross attention -> ctx (fp16)
    {
        int smem = (3 * 64 * 128 + 8 * 64) * (int)sizeof(float);
        cudaFuncSetAttribute(attn_kernel, cudaFuncAttributeMaxDynamicSharedMemorySize, smem);
        attn_kernel<<<dim3(TT / 64, HH, BB), 256, smem>>>(qb, kb, vb, cx);
    }

    // 5) FFN1 + fused exact GELU -> fp16
    gemm_fp16<1><<<(BT / 128) * (DFF / 128), 256, SMEM>>>(cx, w1T, b1, gb, BT, DFF, DD, nullptr, nullptr);

    // 6) FFN2 + fused residual -> fp32 out
    gemm_fp16<2><<<(BT / 128) * (DD / 128), 256, SMEM>>>(gb, w2T, b2, out, BT, DD, DFF, h, alpha);
}